// round 6
// baseline (speedup 1.0000x reference)
#include <cuda_runtime.h>

// Single fused kernel.
// out[n][d] = (x[n]==0 ? 0 : W[x[n]][d]) + PE(n,d)
// PE(n,d): pos=n+1; even d -> cos(pos*w), odd d -> sin(pos*w'), where only
// even exponents e appear: w_e = 10000^{-e/1024}.
//
// Per-thread preamble (cheap, no Payne-Hanek):
//   w        : DP exp (small software poly)
//   rot(w)   : DP sincos, small argument -> fast path
//   seed     : DP multiply (pos0*w) + DP mod-2pi + MUFU __sincosf
// Hot loop: G=8 batched gathers (deep MLP) + fp32 rotation recurrence,
// reseeded exactly every 128 rows (drift ~3.4e-4 rel, well under 1e-3).

#define D_DIM   1024
#define TPB     256
#define ROWS    128
#define G       8

__global__ __launch_bounds__(TPB, 3)
void pe_embed_fused(const int* __restrict__ x,
                    const float* __restrict__ W,
                    float* __restrict__ out,
                    int N)
{
    __shared__ int sx[ROWS];

    const int chunk = blockIdx.x;
    const int n0 = chunk * ROWS;
    const int t  = threadIdx.x;

    if (t < ROWS) {
        int n = n0 + t;
        sx[t] = (n < N) ? x[n] : 0;
    }

    // states m=0..2 use exponent e = 4t + 2m
    float s[3], c[3], sw[3], cw[3];
    {
        const double LOG1E4  = 9.210340371976184;        // ln(10000)
        const double TWO_PI  = 6.283185307179586476925287;
        const double INV_2PI = 0.15915494309189533576888;
        const double pos0    = (double)(n0 + 1);
#pragma unroll
        for (int m = 0; m < 3; m++) {
            int e = 4 * t + 2 * m;
            double w = exp(-(double)e * (LOG1E4 / (double)D_DIM));
            // unit rotation (small arg: DP fast path, no range reduction pain)
            double swd, cwd;
            sincos(w, &swd, &cwd);
            sw[m] = (float)swd;
            cw[m] = (float)cwd;
            // seed angle: exact-in-DP product + mod 2pi, then MUFU sincos
            double ang = pos0 * w;
            ang -= TWO_PI * floor(ang * INV_2PI);
            float ss, cc;
            __sincosf((float)ang, &ss, &cc);
            s[m] = ss;
            c[m] = cc;
        }
    }
    __syncthreads();

    const float4* __restrict__ Wv = (const float4*)W;
    float4* outv = (float4*)out;

    const int nr = (N - n0 < ROWS) ? (N - n0) : ROWS;
    const long obase = (long)n0 * (D_DIM / 4) + t;

    if (nr == ROWS) {
        // fast path: batch G row-gathers before compute/store -> deep MLP
        for (int rb = 0; rb < ROWS; rb += G) {
            int    idx[G];
            float4 e[G];
#pragma unroll
            for (int j = 0; j < G; j++) idx[j] = sx[rb + j];
#pragma unroll
            for (int j = 0; j < G; j++)   // unconditional: row 0 is valid memory
                e[j] = __ldg(&Wv[(long)idx[j] * (D_DIM / 4) + t]);
#pragma unroll
            for (int j = 0; j < G; j++) {
                float msk = (idx[j] == 0) ? 0.f : 1.f;   // padding row -> zero
                float4 o;
                o.x = fmaf(e[j].x, msk, c[0]);
                o.y = fmaf(e[j].y, msk, s[1]);
                o.z = fmaf(e[j].z, msk, c[1]);
                o.w = fmaf(e[j].w, msk, s[2]);
                __stcs(&outv[obase + (long)(rb + j) * (D_DIM / 4)], o);
#pragma unroll
                for (int m = 0; m < 3; m++) {
                    float ns = fmaf(s[m], cw[m],  c[m] * sw[m]);
                    float nc = fmaf(c[m], cw[m], -s[m] * sw[m]);
                    s[m] = ns; c[m] = nc;
                }
            }
        }
    } else {
        for (int r = 0; r < nr; r++) {
            int idx = sx[r];
            float4 e = make_float4(0.f, 0.f, 0.f, 0.f);
            if (idx != 0) e = __ldg(&Wv[(long)idx * (D_DIM / 4) + t]);
            float4 o;
            o.x = e.x + c[0];
            o.y = e.y + s[1];
            o.z = e.z + c[1];
            o.w = e.w + s[2];
            __stcs(&outv[obase + (long)r * (D_DIM / 4)], o);
#pragma unroll
            for (int m = 0; m < 3; m++) {
                float ns = fmaf(s[m], cw[m],  c[m] * sw[m]);
                float nc = fmaf(c[m], cw[m], -s[m] * sw[m]);
                s[m] = ns; c[m] = nc;
            }
        }
    }
}

extern "C" void kernel_launch(void* const* d_in, const int* in_sizes, int n_in,
                              void* d_out, int out_size)
{
    const int*   x;
    const float* W;
    int N;
    if (in_sizes[0] < in_sizes[1]) {
        x = (const int*)d_in[0];  W = (const float*)d_in[1];  N = in_sizes[0];
    } else {
        x = (const int*)d_in[1];  W = (const float*)d_in[0];  N = in_sizes[1];
    }
    int nchunks = (N + ROWS - 1) / ROWS;
    pe_embed_fused<<<nchunks, TPB>>>(x, W, (float*)d_out, N);
}